// round 1
// baseline (speedup 1.0000x reference)
#include <cuda_runtime.h>
#include <cstdint>

// Problem constants
#define NB 16       // batch
#define BB 288      // input capsules (reduced with softmax(a), max/min, Sum)
#define NC 32       // output capsules (softmax over this dim)
#define NP 16       // pose dim (P2, reduced in norm/squash/dot)
#define NF 36       // f*f spatial positions (parallel)
#define NCHUNK 9    // B chunks per batch
#define BCH 32      // B per chunk (288/9)
#define SLICE (NC*NP*NF)   // 18432 floats = one (b,B) slice of u
#define CF (NC*NF)         // 1152
#define THREADS 512
#define SPT (SLICE/THREADS)  // 36 S-accumulator elements per thread

// ---------------- device scratch (static, no allocation) ----------------
__device__ float g_asm[NB*BB*NF];            // softmax_B(a): c0 weights
__device__ float g_Spart[NB*NCHUNK*SLICE];   // per-chunk partial S sums
__device__ float g_w[NB*SLICE];              // running sum of v_j (per b,C,P2,f)
__device__ float g_s[NB*CF];                 // 1/(mx-mn) per (b,C,f)
__device__ int   g_mx[NB*CF];
__device__ int   g_mn[NB*CF];

// ---------------- init: mx/mn ----------------
__global__ void init_kernel() {
    int g = blockIdx.x * blockDim.x + threadIdx.x;
    if (g < NB*CF) {
        g_mx[g] = 0;            // norms >= 0, int-punned compare valid
        g_mn[g] = 0x7F800000;   // +inf
    }
}

// ---------------- softmax of a over B, per (b, f) ----------------
__global__ void asm_kernel(const float* __restrict__ a) {
    __shared__ float red[BB];
    int bf = blockIdx.x;            // 0..NB*NF-1
    int bi = bf / NF, f = bf - bi*NF;
    int t = threadIdx.x;            // 0..287 (= Bi)
    float x = a[(bi*BB + t)*NF + f];
    red[t] = x; __syncthreads();
    for (int st = 256; st >= 1; st >>= 1) {
        if (t < st && t + st < BB) red[t] = fmaxf(red[t], red[t + st]);
        __syncthreads();
    }
    float m = red[0]; __syncthreads();
    float e = __expf(x - m);
    red[t] = e; __syncthreads();
    for (int st = 256; st >= 1; st >>= 1) {
        if (t < st && t + st < BB) red[t] += red[t + st];
        __syncthreads();
    }
    g_asm[(bi*BB + t)*NF + f] = e / red[0];
}

// ---------------- pass 0: per-(B,C,f) norms (-> min/max) + S0 = sum_B c0*u ----------------
__global__ __launch_bounds__(THREADS, 1)
void pass0_kernel(const float* __restrict__ u) {
    extern __shared__ float sh[];
    float* u_sm  = sh;                 // SLICE
    float* bmax  = sh + SLICE;         // CF
    float* bmin  = bmax + CF;          // CF
    float* a_row = bmin + CF;          // 64 (36 used)

    int bi = blockIdx.x / NCHUNK, ch = blockIdx.x % NCHUNK;
    int tid = threadIdx.x;

    for (int idx = tid; idx < CF; idx += THREADS) { bmax[idx] = -1e30f; bmin[idx] = 1e30f; }

    float S[SPT];
    #pragma unroll
    for (int j = 0; j < SPT; j++) S[j] = 0.f;

    for (int Bi = ch*BCH; Bi < ch*BCH + BCH; Bi++) {
        const float4* up = (const float4*)(u + (size_t)(bi*BB + Bi)*SLICE);
        __syncthreads();
        #pragma unroll
        for (int j = 0; j < SLICE/4/THREADS; j++)
            ((float4*)u_sm)[tid + j*THREADS] = up[tid + j*THREADS];
        if (tid < NF) a_row[tid] = g_asm[(bi*BB + Bi)*NF + tid];
        __syncthreads();

        // norm over P2 per (C, f); running min/max over B (owner-thread private)
        for (int idx = tid; idx < CF; idx += THREADS) {
            int Ci = idx / NF, f = idx - Ci*NF;
            float acc = 0.f;
            #pragma unroll
            for (int p = 0; p < NP; p++) {
                float x = u_sm[(Ci*NP + p)*NF + f];
                acc = fmaf(x, x, acc);
            }
            float nrm = sqrtf(acc);
            bmax[idx] = fmaxf(bmax[idx], nrm);
            bmin[idx] = fminf(bmin[idx], nrm);
        }
        // S0 += c0[f] * u  (c0 = softmax_B(a), no C dependence)
        #pragma unroll
        for (int j = 0; j < SPT; j++) {
            int e = tid + j*THREADS;
            S[j] = fmaf(a_row[e % NF], u_sm[e], S[j]);
        }
    }
    float* sp = g_Spart + (size_t)blockIdx.x * SLICE;
    #pragma unroll
    for (int j = 0; j < SPT; j++) sp[tid + j*THREADS] = S[j];
    __syncthreads();
    for (int idx = tid; idx < CF; idx += THREADS) {
        atomicMax(&g_mx[bi*CF + idx], __float_as_int(bmax[idx]));
        atomicMin(&g_mn[bi*CF + idx], __float_as_int(bmin[idx]));
    }
}

// ---------------- routing pass i>0: r from w, softmax over C, S_i = sum_B c_i*u ----------------
__global__ __launch_bounds__(THREADS, 1)
void pass_kernel(const float* __restrict__ u) {
    extern __shared__ float sh[];
    float* u_sm  = sh;                 // SLICE
    float* w_sm  = sh + SLICE;         // SLICE
    float* s_sm  = w_sm + SLICE;       // CF
    float* r_sm  = s_sm + CF;          // CF
    float* c_sm  = r_sm + CF;          // CF
    float* a_row = c_sm + CF;          // 64

    int bi = blockIdx.x / NCHUNK, ch = blockIdx.x % NCHUNK;
    int tid = threadIdx.x;

    for (int j = tid; j < SLICE; j += THREADS) w_sm[j] = g_w[bi*SLICE + j];
    for (int j = tid; j < CF;    j += THREADS) s_sm[j] = g_s[bi*CF + j];

    float S[SPT];
    #pragma unroll
    for (int j = 0; j < SPT; j++) S[j] = 0.f;

    for (int Bi = ch*BCH; Bi < ch*BCH + BCH; Bi++) {
        const float4* up = (const float4*)(u + (size_t)(bi*BB + Bi)*SLICE);
        __syncthreads();
        #pragma unroll
        for (int j = 0; j < SLICE/4/THREADS; j++)
            ((float4*)u_sm)[tid + j*THREADS] = up[tid + j*THREADS];
        if (tid < NF) a_row[tid] = g_asm[(bi*BB + Bi)*NF + tid];
        __syncthreads();

        // r[C,f] = s[C,f] * sum_p u[C,p,f]*w[C,p,f]
        for (int idx = tid; idx < CF; idx += THREADS) {
            int Ci = idx / NF, f = idx - Ci*NF;
            float acc = 0.f;
            #pragma unroll
            for (int p = 0; p < NP; p++) {
                int o = (Ci*NP + p)*NF + f;
                acc = fmaf(u_sm[o], w_sm[o], acc);
            }
            r_sm[idx] = acc * s_sm[idx];
        }
        __syncthreads();
        // softmax over C per f; c = softmax * a_sm * NC
        if (tid < NF) {
            float m = -1e30f;
            #pragma unroll
            for (int Ci = 0; Ci < NC; Ci++) m = fmaxf(m, r_sm[Ci*NF + tid]);
            float sum = 0.f;
            #pragma unroll
            for (int Ci = 0; Ci < NC; Ci++) {
                float e = __expf(r_sm[Ci*NF + tid] - m);
                c_sm[Ci*NF + tid] = e;
                sum += e;
            }
            float sc = a_row[tid] * (float)NC / sum;
            #pragma unroll
            for (int Ci = 0; Ci < NC; Ci++) c_sm[Ci*NF + tid] *= sc;
        }
        __syncthreads();
        #pragma unroll
        for (int j = 0; j < SPT; j++) {
            int e = tid + j*THREADS;
            S[j] = fmaf(c_sm[(e / (NP*NF))*NF + (e % NF)], u_sm[e], S[j]);
        }
    }
    float* sp = g_Spart + (size_t)blockIdx.x * SLICE;
    #pragma unroll
    for (int j = 0; j < SPT; j++) sp[tid + j*THREADS] = S[j];
}

// ---------------- reduce partials, squash, update w / write output ----------------
template<int IT>
__global__ void v_kernel(float* __restrict__ out) {
    int g = blockIdx.x * blockDim.x + threadIdx.x;   // 0..NB*CF-1
    if (g >= NB*CF) return;
    int bi = g / CF;
    int idx = g - bi*CF;
    int Ci = idx / NF, f = idx - Ci*NF;

    float s;
    if (IT == 0) {
        float mx = __int_as_float(g_mx[g]);
        float mn = __int_as_float(g_mn[g]);
        s = 1.f / (mx - mn);
        g_s[g] = s;
    } else {
        s = g_s[g];
    }

    float v[NP];
    float sn = 0.f;
    #pragma unroll
    for (int p = 0; p < NP; p++) {
        float acc = 0.f;
        #pragma unroll
        for (int ch = 0; ch < NCHUNK; ch++)
            acc += g_Spart[(size_t)(bi*NCHUNK + ch)*SLICE + (Ci*NP + p)*NF + f];
        acc *= s;
        v[p] = acc;
        sn = fmaf(acc, acc, sn);
    }
    float fac = (sn / (1.f + sn)) * rsqrtf(sn + 1e-5f);

    if (IT < 2) {
        #pragma unroll
        for (int p = 0; p < NP; p++) {
            float vp = v[p] * fac;
            int o = bi*SLICE + (Ci*NP + p)*NF + f;
            g_w[o] = (IT == 0) ? vp : (g_w[o] + vp);
        }
    } else {
        float a2 = 0.f;
        #pragma unroll
        for (int p = 0; p < NP; p++) {
            float vp = v[p] * fac;
            out[((bi*NC + Ci)*NP + p)*NF + f] = vp;
            a2 = fmaf(vp, vp, a2);
        }
        out[NB*NC*NP*NF + (bi*NC + Ci)*NF + f] = sqrtf(a2);
    }
}

// ---------------- launch ----------------
extern "C" void kernel_launch(void* const* d_in, const int* in_sizes, int n_in,
                              void* d_out, int out_size) {
    const float* u = (const float*)d_in[0];
    const float* a = (const float*)d_in[1];
    // defensive: identify inputs by size (u is the big one)
    if (n_in >= 2 && in_sizes[0] < in_sizes[1]) {
        u = (const float*)d_in[1];
        a = (const float*)d_in[0];
    }
    float* out = (float*)d_out;

    const int SMEM0 = (SLICE + 2*CF + 64) * sizeof(float);      // ~87.5 KB
    const int SMEM1 = (2*SLICE + 3*CF + 64) * sizeof(float);    // ~161.5 KB
    cudaFuncSetAttribute(pass0_kernel, cudaFuncAttributeMaxDynamicSharedMemorySize, SMEM0);
    cudaFuncSetAttribute(pass_kernel,  cudaFuncAttributeMaxDynamicSharedMemorySize, SMEM1);

    init_kernel<<<(NB*CF + 255)/256, 256>>>();
    asm_kernel<<<NB*NF, BB>>>(a);

    pass0_kernel<<<NB*NCHUNK, THREADS, SMEM0>>>(u);
    v_kernel<0><<<(NB*CF + 255)/256, 256>>>(out);

    pass_kernel<<<NB*NCHUNK, THREADS, SMEM1>>>(u);
    v_kernel<1><<<(NB*CF + 255)/256, 256>>>(out);

    pass_kernel<<<NB*NCHUNK, THREADS, SMEM1>>>(u);
    v_kernel<2><<<(NB*CF + 255)/256, 256>>>(out);
}